// round 17
// baseline (speedup 1.0000x reference)
#include <cuda_runtime.h>
#include <cuda_bf16.h>
#include <cstdint>

// ---------------------------------------------------------------------------
// GraphPooling: 3-layer GAT (single head) + final projection.
// Round 17: revert tcgen05 (not supported by harness PTX target).
//           Round-15 config + attn_agg gather unrolled x8 for deeper MLP.
// ---------------------------------------------------------------------------

#define NMAX 50000
#define EMAX 800000
#define FMAX 128
#define SCAN_B 1024
#define NB_MAX 64

__device__ float g_hbuf  [NMAX * FMAX];
__device__ float g_actbuf[NMAX * FMAX];
__device__ float g_as   [NMAX];
__device__ float g_ad   [NMAX];
__device__ int   g_csrc [EMAX];
__device__ int   g_rp   [NMAX + 1];
__device__ int   g_cur  [NMAX];
__device__ int   g_cnt  [NMAX];
__device__ int   g_tscan[NMAX];
__device__ int   g_bsum [NB_MAX];
__device__ float g_gmax [4];
__device__ float g_ST   [64 * 512];

__device__ __forceinline__ float leaky02(float v) { return v > 0.f ? v : 0.2f * v; }

__device__ __forceinline__ void atomicMaxFloat(float* addr, float val) {
    if (val >= 0.f) atomicMax((int*)addr, __float_as_int(val));
    else            atomicMin((unsigned int*)addr, __float_as_uint(val));
}

__device__ __forceinline__ uint32_t pack_bf16x2(float f0, float f1) {
    __nv_bfloat162 h = __floats2bfloat162_rn(f0, f1);
    return *reinterpret_cast<uint32_t*>(&h);
}

__device__ __forceinline__ void split_bf(float v, float& hi, float& lo) {
    __nv_bfloat16 h = __float2bfloat16_rn(v);
    hi = __bfloat162float(h);
    lo = v - hi;
}

__device__ __forceinline__ void mma_bf16(float c[4],
                                         uint32_t a0, uint32_t a1, uint32_t a2, uint32_t a3,
                                         uint32_t b0, uint32_t b1) {
    asm("mma.sync.aligned.m16n8k16.row.col.f32.bf16.bf16.f32 "
        "{%0,%1,%2,%3}, {%4,%5,%6,%7}, {%8,%9}, {%0,%1,%2,%3};"
        : "+f"(c[0]), "+f"(c[1]), "+f"(c[2]), "+f"(c[3])
        : "r"(a0), "r"(a1), "r"(a2), "r"(a3), "r"(b0), "r"(b1));
}

// ---------------------------------------------------------------------------
// Tensor GEMM (3xBF16, m16n8k16, BK=32): C[M,Ncols] = A[M,K] @ B[K,Ncols].
// ALPHA: also emits oas/oad row dots and atomics gmax = max(oas).
// ---------------------------------------------------------------------------
template<int BM, int BN, int WM, int WN, bool ALPHA>
__global__ void __launch_bounds__(256)
mma_gemm_kernel(const float* __restrict__ A, const float* __restrict__ B,
                float* __restrict__ C,
                const float* __restrict__ avs, const float* __restrict__ avd,
                float* __restrict__ oas, float* __restrict__ oad,
                float* __restrict__ gmax,
                int M, int Ncols, int K)
{
    constexpr int BK = 32;
    constexpr int WARPS_N = BN / WN;
    static_assert((BM / WM) * (BN / WN) == 8, "8 warps");
    constexpr int MT = WM / 16;
    constexpr int NT = WN / 8;
    constexpr int ASS = BK / 2 + 4;
    constexpr int BSS = BN + 8;
    constexpr int A_PER = (BM * (BK / 4)) / 256;
    constexpr int B_PAIRS = ((BK / 2) * (BN / 4)) / 256;

    extern __shared__ uint32_t sm[];
    uint32_t* As_hi = sm;
    uint32_t* As_lo = As_hi + 2 * BM * ASS;
    uint32_t* Bs_hi = As_lo + 2 * BM * ASS;
    uint32_t* Bs_lo = Bs_hi + 2 * (BK / 2) * BSS;
    float*    red_s = (float*)(Bs_lo + 2 * (BK / 2) * BSS);
    float*    red_d = red_s + BM;

    const int tid  = threadIdx.x;
    const int lane = tid & 31;
    const int warp = tid >> 5;
    const int wm   = (warp / WARPS_N) * WM;
    const int wn   = (warp % WARPS_N) * WN;
    const int m0   = blockIdx.x * BM;
    const int n0   = blockIdx.y * BN;
    const int gid  = lane >> 2;
    const int tig  = lane & 3;

    if (ALPHA) {
        for (int i = tid; i < BM; i += 256) { red_s[i] = 0.f; red_d[i] = 0.f; }
    }

    float c[MT][NT][4];
#pragma unroll
    for (int i = 0; i < MT; i++)
#pragma unroll
        for (int j = 0; j < NT; j++) {
            c[i][j][0] = 0.f; c[i][j][1] = 0.f; c[i][j][2] = 0.f; c[i][j][3] = 0.f;
        }

    const int a_row = tid / (BK / 4);
    const int a_kq  = tid % (BK / 4);
    const int b_kp  = tid / (BN / 4);
    const int b_c4  = tid % (BN / 4);

    float4 areg[A_PER];
    float4 breg[B_PAIRS][2];

    auto load_tile = [&](int k0) {
#pragma unroll
        for (int i = 0; i < A_PER; i++) {
            int row = a_row + i * (256 / (BK / 4));
            int gr  = m0 + row;
            areg[i] = make_float4(0.f, 0.f, 0.f, 0.f);
            if (gr < M) areg[i] = *(const float4*)(A + (size_t)gr * K + k0 + a_kq * 4);
        }
#pragma unroll
        for (int i = 0; i < B_PAIRS; i++) {
            int kp = b_kp + i * (256 / (BN / 4));
            int gk = k0 + 2 * kp;
            breg[i][0] = *(const float4*)(B + (size_t)gk * Ncols + n0 + b_c4 * 4);
            breg[i][1] = *(const float4*)(B + (size_t)(gk + 1) * Ncols + n0 + b_c4 * 4);
        }
    };

    auto store_tile = [&](int st) {
#pragma unroll
        for (int i = 0; i < A_PER; i++) {
            int row = a_row + i * (256 / (BK / 4));
            float4 v = areg[i];
            float h0, l0, h1, l1, h2, l2, h3, l3;
            split_bf(v.x, h0, l0); split_bf(v.y, h1, l1);
            split_bf(v.z, h2, l2); split_bf(v.w, h3, l3);
            uint32_t* hp = &As_hi[(st * BM + row) * ASS + a_kq * 2];
            uint32_t* lp = &As_lo[(st * BM + row) * ASS + a_kq * 2];
            *(uint2*)hp = make_uint2(pack_bf16x2(h0, h1), pack_bf16x2(h2, h3));
            *(uint2*)lp = make_uint2(pack_bf16x2(l0, l1), pack_bf16x2(l2, l3));
        }
#pragma unroll
        for (int i = 0; i < B_PAIRS; i++) {
            int kp = b_kp + i * (256 / (BN / 4));
            float4 v0 = breg[i][0], v1 = breg[i][1];
            float h0a, l0a, h1a, l1a, h2a, l2a, h3a, l3a;
            float h0b, l0b, h1b, l1b, h2b, l2b, h3b, l3b;
            split_bf(v0.x, h0a, l0a); split_bf(v0.y, h1a, l1a);
            split_bf(v0.z, h2a, l2a); split_bf(v0.w, h3a, l3a);
            split_bf(v1.x, h0b, l0b); split_bf(v1.y, h1b, l1b);
            split_bf(v1.z, h2b, l2b); split_bf(v1.w, h3b, l3b);
            uint32_t* hp = &Bs_hi[(st * (BK / 2) + kp) * BSS + b_c4 * 4];
            uint32_t* lp = &Bs_lo[(st * (BK / 2) + kp) * BSS + b_c4 * 4];
            *(uint4*)hp = make_uint4(pack_bf16x2(h0a, h0b), pack_bf16x2(h1a, h1b),
                                     pack_bf16x2(h2a, h2b), pack_bf16x2(h3a, h3b));
            *(uint4*)lp = make_uint4(pack_bf16x2(l0a, l0b), pack_bf16x2(l1a, l1b),
                                     pack_bf16x2(l2a, l2b), pack_bf16x2(l3a, l3b));
        }
    };

    load_tile(0);
    store_tile(0);
    __syncthreads();

    const int T = K / BK;
    for (int t = 0; t < T; t++) {
        int buf = t & 1;
        if (t + 1 < T) load_tile((t + 1) * BK);

#pragma unroll
        for (int ks2 = 0; ks2 < BK / 16; ks2++) {
            uint32_t ah[MT][4], al[MT][4];
#pragma unroll
            for (int mt = 0; mt < MT; mt++) {
                int r = (buf * BM + wm + mt * 16 + gid) * ASS + ks2 * 8;
                ah[mt][0] = As_hi[r           + tig    ];
                ah[mt][1] = As_hi[r + 8 * ASS + tig    ];
                ah[mt][2] = As_hi[r           + tig + 4];
                ah[mt][3] = As_hi[r + 8 * ASS + tig + 4];
                al[mt][0] = As_lo[r           + tig    ];
                al[mt][1] = As_lo[r + 8 * ASS + tig    ];
                al[mt][2] = As_lo[r           + tig + 4];
                al[mt][3] = As_lo[r + 8 * ASS + tig + 4];
            }
            uint32_t bh[NT][2], bl[NT][2];
#pragma unroll
            for (int nt = 0; nt < NT; nt++) {
                int cc  = wn + nt * 8 + gid;
                int rb0 = (buf * (BK / 2) + ks2 * 8 + tig)     * BSS + cc;
                int rb1 = (buf * (BK / 2) + ks2 * 8 + tig + 4) * BSS + cc;
                bh[nt][0] = Bs_hi[rb0]; bh[nt][1] = Bs_hi[rb1];
                bl[nt][0] = Bs_lo[rb0]; bl[nt][1] = Bs_lo[rb1];
            }
#pragma unroll
            for (int nt = 0; nt < NT; nt++)
#pragma unroll
                for (int mt = 0; mt < MT; mt++)
                    mma_bf16(c[mt][nt], ah[mt][0], ah[mt][1], ah[mt][2], ah[mt][3],
                             bh[nt][0], bh[nt][1]);
#pragma unroll
            for (int nt = 0; nt < NT; nt++)
#pragma unroll
                for (int mt = 0; mt < MT; mt++)
                    mma_bf16(c[mt][nt], al[mt][0], al[mt][1], al[mt][2], al[mt][3],
                             bh[nt][0], bh[nt][1]);
#pragma unroll
            for (int nt = 0; nt < NT; nt++)
#pragma unroll
                for (int mt = 0; mt < MT; mt++)
                    mma_bf16(c[mt][nt], ah[mt][0], ah[mt][1], ah[mt][2], ah[mt][3],
                             bl[nt][0], bl[nt][1]);
        }

        if (t + 1 < T) {
            store_tile(buf ^ 1);
            __syncthreads();
        }
    }

#pragma unroll
    for (int mt = 0; mt < MT; mt++) {
        int r0l = wm + mt * 16 + gid;
        int r1l = r0l + 8;
        int gr0 = m0 + r0l;
        int gr1 = m0 + r1l;
        float ps0 = 0.f, pd0 = 0.f, ps1 = 0.f, pd1 = 0.f;
#pragma unroll
        for (int nt = 0; nt < NT; nt++) {
            int cb = wn + nt * 8 + tig * 2;
            if (gr0 < M) {
                float2 v = make_float2(c[mt][nt][0], c[mt][nt][1]);
                *(float2*)(C + (size_t)gr0 * Ncols + n0 + cb) = v;
            }
            if (gr1 < M) {
                float2 v = make_float2(c[mt][nt][2], c[mt][nt][3]);
                *(float2*)(C + (size_t)gr1 * Ncols + n0 + cb) = v;
            }
            if (ALPHA) {
                float s0 = __ldg(&avs[cb]), s1 = __ldg(&avs[cb + 1]);
                float d0 = __ldg(&avd[cb]), d1 = __ldg(&avd[cb + 1]);
                ps0 = fmaf(c[mt][nt][0], s0, fmaf(c[mt][nt][1], s1, ps0));
                pd0 = fmaf(c[mt][nt][0], d0, fmaf(c[mt][nt][1], d1, pd0));
                ps1 = fmaf(c[mt][nt][2], s0, fmaf(c[mt][nt][3], s1, ps1));
                pd1 = fmaf(c[mt][nt][2], d0, fmaf(c[mt][nt][3], d1, pd1));
            }
        }
        if (ALPHA) {
#pragma unroll
            for (int off = 1; off < 4; off <<= 1) {
                ps0 += __shfl_xor_sync(0xffffffffu, ps0, off);
                pd0 += __shfl_xor_sync(0xffffffffu, pd0, off);
                ps1 += __shfl_xor_sync(0xffffffffu, ps1, off);
                pd1 += __shfl_xor_sync(0xffffffffu, pd1, off);
            }
            if (tig == 0) {
                atomicAdd(&red_s[r0l], ps0);
                atomicAdd(&red_d[r0l], pd0);
                atomicAdd(&red_s[r1l], ps1);
                atomicAdd(&red_d[r1l], pd1);
            }
        }
    }
    if (ALPHA) {
        __syncthreads();
        float lmax = -3.4e38f;
        for (int i = tid; i < BM; i += 256) {
            int gr = m0 + i;
            if (gr < M) {
                float vs = red_s[i];
                oas[gr] = vs;
                oad[gr] = red_d[i];
                lmax = fmaxf(lmax, vs);
            }
        }
#pragma unroll
        for (int o = 16; o; o >>= 1)
            lmax = fmaxf(lmax, __shfl_xor_sync(0xffffffffu, lmax, o));
        if ((tid & 31) == 0) atomicMaxFloat(gmax, lmax);
    }
}

static inline int mma_smem_bytes(int BM, int BN) {
    int BK = 32;
    int ASS = BK / 2 + 4, BSS = BN + 8;
    return (2 * BM * ASS * 2 + 2 * (BK / 2) * BSS * 2 + 2 * BM) * 4;
}

// ---------------------------------------------------------------------------
// CSR build
// ---------------------------------------------------------------------------
__global__ void init_gmax_kernel(float* __restrict__ gmax)
{
    if (threadIdx.x < 4) gmax[threadIdx.x] = -__int_as_float(0x7F800000);
}

__global__ void zero_cnt_kernel(int* __restrict__ cnt, int N)
{
    int i = blockIdx.x * blockDim.x + threadIdx.x;
    if (i < N) cnt[i] = 0;
}

__global__ void hist_kernel(const int* __restrict__ ei, int* __restrict__ cnt, int E)
{
    int i = (blockIdx.x * blockDim.x + threadIdx.x) * 4;
    if (i + 3 < E) {
        int4 d = *(const int4*)(ei + E + i);
        atomicAdd(&cnt[d.x], 1);
        atomicAdd(&cnt[d.y], 1);
        atomicAdd(&cnt[d.z], 1);
        atomicAdd(&cnt[d.w], 1);
    } else {
        for (int e = i; e < E; e++) atomicAdd(&cnt[ei[E + e]], 1);
    }
}

__global__ void __launch_bounds__(SCAN_B)
scan_phase1(const int* __restrict__ cnt, int* __restrict__ tscan,
            int* __restrict__ bsum, int N)
{
    __shared__ int sh[SCAN_B];
    int t = threadIdx.x;
    int i = blockIdx.x * SCAN_B + t;
    int v = (i < N) ? cnt[i] : 0;
    sh[t] = v;
    __syncthreads();
#pragma unroll
    for (int off = 1; off < SCAN_B; off <<= 1) {
        int u = (t >= off) ? sh[t - off] : 0;
        __syncthreads();
        sh[t] += u;
        __syncthreads();
    }
    if (i < N) tscan[i] = sh[t];
    if (t == SCAN_B - 1) bsum[blockIdx.x] = sh[t];
}

__global__ void __launch_bounds__(NB_MAX)
scan_phase2(int* __restrict__ bsum, int nb)
{
    __shared__ int sh[NB_MAX];
    int t = threadIdx.x;
    int v = (t < nb) ? bsum[t] : 0;
    sh[t] = v;
    __syncthreads();
#pragma unroll
    for (int off = 1; off < NB_MAX; off <<= 1) {
        int u = (t >= off) ? sh[t - off] : 0;
        __syncthreads();
        sh[t] += u;
        __syncthreads();
    }
    if (t < nb) bsum[t] = sh[t] - v;
}

__global__ void __launch_bounds__(SCAN_B)
scan_phase3(const int* __restrict__ cnt, const int* __restrict__ tscan,
            const int* __restrict__ bsum, int* __restrict__ rp,
            int* __restrict__ cur, int N)
{
    int t = threadIdx.x;
    int i = blockIdx.x * SCAN_B + t;
    if (i < N) {
        int incl = tscan[i] + bsum[blockIdx.x];
        int excl = incl - cnt[i];
        rp[i]  = excl;
        cur[i] = excl;
        if (i == N - 1) rp[N] = incl;
    }
}

__global__ void scatter_kernel(const int* __restrict__ ei, int* __restrict__ cur,
                               int* __restrict__ csrc, int E)
{
    int i = (blockIdx.x * blockDim.x + threadIdx.x) * 4;
    if (i + 3 < E) {
        int4 s = *(const int4*)(ei + i);
        int4 d = *(const int4*)(ei + E + i);
        csrc[atomicAdd(&cur[d.x], 1)] = s.x;
        csrc[atomicAdd(&cur[d.y], 1)] = s.y;
        csrc[atomicAdd(&cur[d.z], 1)] = s.z;
        csrc[atomicAdd(&cur[d.w], 1)] = s.w;
    } else {
        for (int e = i; e < E; e++)
            csrc[atomicAdd(&cur[ei[E + e]], 1)] = ei[e];
    }
}

// ---------------------------------------------------------------------------
// Fused attention softmax + aggregation. SG = F/4 lanes per node,
// subgroup-masked sync, gather unrolled x8 for deeper MLP.
// ---------------------------------------------------------------------------
template<int F>
__global__ void __launch_bounds__(256)
attn_agg_kernel(const int* __restrict__ rp,
                const int* __restrict__ csrc,
                const float* __restrict__ as_,
                const float* __restrict__ ad_,
                const float* __restrict__ gmaxp,
                const float* __restrict__ h,
                const float* __restrict__ bias,
                float* __restrict__ out, int N, int do_leaky)
{
    constexpr int SG  = F / 4;
    constexpr int NPW = 32 / SG;
    __shared__ float sw[8 * NPW][SG];
    __shared__ int   ss[8 * NPW][SG];

    int tidg = blockIdx.x * blockDim.x + threadIdx.x;
    int lane = threadIdx.x & 31;
    int sub  = lane / SG;
    int l    = lane % SG;
    int grp  = (threadIdx.x >> 5) * NPW + sub;
    int node = (tidg >> 5) * NPW + sub;
    if (node >= N) return;

    const unsigned submask = (SG == 32) ? 0xffffffffu
                                        : (((1u << SG) - 1u) << (sub * SG));

    int j0 = rp[node], j1 = rp[node + 1];
    float add = ad_[node];
    float m   = leaky02(__ldg(gmaxp) + add);

    float ws = expf(leaky02(as_[node] + add) - m);
    float4 hv = *(const float4*)(h + (size_t)node * F + l * 4);
    float ax = ws * hv.x, ay = ws * hv.y, az = ws * hv.z, aw = ws * hv.w;

    float sum = 0.f;
    for (int c = j0; c < j1; c += SG) {
        int jj = c + l;
        float w = 0.f;
        int   s = 0;
        if (jj < j1) {
            s = __ldg(&csrc[jj]);
            w = expf(leaky02(__ldg(&as_[s]) + add) - m);
        }
        sum += w;
        sw[grp][l] = w;
        ss[grp][l] = s;
        __syncwarp(submask);
        int cnt = min(SG, j1 - c);
        int k = 0;
        for (; k + 7 < cnt; k += 8) {
            float wr[8];
            int   sr[8];
#pragma unroll
            for (int q = 0; q < 8; q++) { wr[q] = sw[grp][k + q]; sr[q] = ss[grp][k + q]; }
            float4 vr[8];
#pragma unroll
            for (int q = 0; q < 8; q++)
                vr[q] = *(const float4*)(h + (size_t)sr[q] * F + l * 4);
#pragma unroll
            for (int q = 0; q < 8; q++) {
                ax = fmaf(wr[q], vr[q].x, ax);
                ay = fmaf(wr[q], vr[q].y, ay);
                az = fmaf(wr[q], vr[q].z, az);
                aw = fmaf(wr[q], vr[q].w, aw);
            }
        }
        for (; k < cnt; k++) {
            float wk = sw[grp][k];
            int   sk = ss[grp][k];
            float4 v = *(const float4*)(h + (size_t)sk * F + l * 4);
            ax = fmaf(wk, v.x, ax);
            ay = fmaf(wk, v.y, ay);
            az = fmaf(wk, v.z, az);
            aw = fmaf(wk, v.w, aw);
        }
        __syncwarp(submask);
    }
#pragma unroll
    for (int o = SG / 2; o; o >>= 1)
        sum += __shfl_xor_sync(submask, sum, o);

    float inv = 1.f / (sum + ws);
    float4 b = *(const float4*)(bias + l * 4);
    float4 o;
    o.x = ax * inv + b.x;
    o.y = ay * inv + b.y;
    o.z = az * inv + b.z;
    o.w = aw * inv + b.w;
    if (do_leaky) {
        o.x = o.x > 0.f ? o.x : 0.1f * o.x;
        o.y = o.y > 0.f ? o.y : 0.1f * o.y;
        o.z = o.z > 0.f ? o.z : 0.1f * o.z;
        o.w = o.w > 0.f ? o.w : 0.1f * o.w;
    }
    *(float4*)(out + (size_t)node * F + l * 4) = o;
}

__global__ void transpose_S_kernel(const float* __restrict__ S, float* __restrict__ ST)
{
    int i = blockIdx.x * blockDim.x + threadIdx.x;
    if (i < 64 * 512) {
        int k = i / 512, n = i % 512;
        ST[i] = S[n * 64 + k];
    }
}

// ---------------------------------------------------------------------------
// Host
// ---------------------------------------------------------------------------
static inline int cdiv(int a, int b) { return (a + b - 1) / b; }

extern "C" void kernel_launch(void* const* d_in, const int* in_sizes, int n_in,
                              void* d_out, int out_size)
{
    const float* x   = (const float*)d_in[0];
    const int*   ei  = (const int*)d_in[1];   // int32 (JAX x64 disabled)
    const float* W1  = (const float*)d_in[2];
    const float* a1s = (const float*)d_in[3];
    const float* a1d = (const float*)d_in[4];
    const float* b1  = (const float*)d_in[5];
    const float* W2  = (const float*)d_in[6];
    const float* a2s = (const float*)d_in[7];
    const float* a2d = (const float*)d_in[8];
    const float* b2  = (const float*)d_in[9];
    const float* W3  = (const float*)d_in[10];
    const float* a3s = (const float*)d_in[11];
    const float* a3d = (const float*)d_in[12];
    const float* b3  = (const float*)d_in[13];
    const float* S   = (const float*)d_in[14];

    int N = in_sizes[0] / 128;
    int E = in_sizes[1] / 2;

    float *hb, *actb, *pas, *pad_, *pst, *pgm;
    int *pcsrc, *prp, *pcur, *pcnt, *ptscan, *pbsum;
    cudaGetSymbolAddress((void**)&hb,     g_hbuf);
    cudaGetSymbolAddress((void**)&actb,   g_actbuf);
    cudaGetSymbolAddress((void**)&pas,    g_as);
    cudaGetSymbolAddress((void**)&pad_,   g_ad);
    cudaGetSymbolAddress((void**)&pst,    g_ST);
    cudaGetSymbolAddress((void**)&pgm,    g_gmax);
    cudaGetSymbolAddress((void**)&pcsrc,  g_csrc);
    cudaGetSymbolAddress((void**)&prp,    g_rp);
    cudaGetSymbolAddress((void**)&pcur,   g_cur);
    cudaGetSymbolAddress((void**)&pcnt,   g_cnt);
    cudaGetSymbolAddress((void**)&ptscan, g_tscan);
    cudaGetSymbolAddress((void**)&pbsum,  g_bsum);

    const int smem128 = mma_smem_bytes(128, 128);
    const int smem64  = mma_smem_bytes(128, 64);
    cudaFuncSetAttribute(mma_gemm_kernel<128,128,64,32,true>,
                         cudaFuncAttributeMaxDynamicSharedMemorySize, smem128);
    cudaFuncSetAttribute(mma_gemm_kernel<128,128,64,32,false>,
                         cudaFuncAttributeMaxDynamicSharedMemorySize, smem128);
    cudaFuncSetAttribute(mma_gemm_kernel<128,64,32,32,true>,
                         cudaFuncAttributeMaxDynamicSharedMemorySize, smem64);

    init_gmax_kernel<<<1, 32>>>(pgm);

    // --- fork a side stream for the CSR build ---
    cudaStream_t s2;
    cudaStreamCreateWithFlags(&s2, cudaStreamNonBlocking);
    cudaEvent_t evFork, evJoin;
    cudaEventCreateWithFlags(&evFork, cudaEventDisableTiming);
    cudaEventCreateWithFlags(&evJoin, cudaEventDisableTiming);

    cudaEventRecord(evFork, 0);
    cudaStreamWaitEvent(s2, evFork, 0);

    int nb = cdiv(N, SCAN_B);

    zero_cnt_kernel<<<cdiv(N,256), 256, 0, s2>>>(pcnt, N);
    hist_kernel<<<cdiv(cdiv(E,4),256), 256, 0, s2>>>(ei, pcnt, E);
    scan_phase1<<<nb, SCAN_B, 0, s2>>>(pcnt, ptscan, pbsum, N);
    scan_phase2<<<1, NB_MAX, 0, s2>>>(pbsum, nb);
    scan_phase3<<<nb, SCAN_B, 0, s2>>>(pcnt, ptscan, pbsum, prp, pcur, N);
    scatter_kernel<<<cdiv(cdiv(E,4),256), 256, 0, s2>>>(ei, pcur, pcsrc, E);
    transpose_S_kernel<<<cdiv(64*512,256), 256, 0, s2>>>(S, pst);
    cudaEventRecord(evJoin, s2);

    int gm   = cdiv(N, 128);
    int gw   = cdiv(N * 32, 256);   // F=128: warp per node
    int gw64 = cdiv(N * 16, 256);   // F=64: half-warp per node

    // --- layer 1 GEMM runs concurrently with the CSR build ---
    mma_gemm_kernel<128,128,64,32,true><<<dim3(gm,1), 256, smem128>>>(
        x, W1, hb, a1s, a1d, pas, pad_, pgm + 0, N, 128, 128);

    cudaStreamWaitEvent(0, evJoin, 0);

    attn_agg_kernel<128><<<gw, 256>>>(prp, pcsrc, pas, pad_, pgm + 0, hb, b1, actb, N, 1);

    // --- layer 2 ---
    mma_gemm_kernel<128,128,64,32,true><<<dim3(gm,1), 256, smem128>>>(
        actb, W2, hb, a2s, a2d, pas, pad_, pgm + 1, N, 128, 128);
    attn_agg_kernel<128><<<gw, 256>>>(prp, pcsrc, pas, pad_, pgm + 1, hb, b2, actb, N, 1);

    // --- layer 3 (F=64, no inter-layer activation) ---
    mma_gemm_kernel<128,64,32,32,true><<<dim3(gm,1), 256, smem64>>>(
        actb, W3, hb, a3s, a3d, pas, pad_, pgm + 2, N, 64, 128);
    attn_agg_kernel<64><<<gw64, 256>>>(prp, pcsrc, pas, pad_, pgm + 2, hb, b3, actb, N, 0);

    // --- final projection: [N,64] @ [64,512] ---
    mma_gemm_kernel<128,128,64,32,false><<<dim3(gm,4), 256, smem128>>>(
        actb, pst, (float*)d_out, nullptr, nullptr, nullptr, nullptr, nullptr,
        N, 512, 64);
}